// round 2
// baseline (speedup 1.0000x reference)
#include <cuda_runtime.h>
#include <cuda_bf16.h>
#include <cstddef>

#define V    6912
#define G4   27648   // 4*V
#define BSZ  16
#define TT   8
#define TR   4
#define KC   384     // recurrence smem chunk (V = 18*KC, KC = 3*128)

// ---------------- device scratch (no allocation allowed) ----------------
__device__ float g_xg[TT * BSZ * G4];   // [t][b][4V] gate preactivations from x
__device__ float g_h0[BSZ * V];
__device__ float g_h1[BSZ * V];
__device__ float g_c [BSZ * V];
__device__ float g_hd[BSZ * TR * V];    // decoder h_d, row m = b*4+tr

__device__ __forceinline__ float sigf(float x) { return 1.0f / (1.0f + expf(-x)); }

// =====================================================================
// K1: xg[t][b][n] = sum_k x[b][t][k] * W_ih_enc[n][k] + b_enc[n]
// M=128 (rows of x, m = b*8+t), N=27648, K=6912.  BM=128, BN=64, BK=32,
// 128 threads, 8x8 micro-tile. Compute-bound fp32.
// =====================================================================
__global__ __launch_bounds__(128) void gemm_xg_kernel(
    const float* __restrict__ x, const float* __restrict__ W,
    const float* __restrict__ bias)
{
    __shared__ float sA[32][132];  // [k][m], padded
    __shared__ float sB[32][68];   // [k][n]

    const int tid = threadIdx.x;
    const int n0  = blockIdx.x * 64;
    const int tx  = tid & 7;       // n
    const int ty  = tid >> 3;      // m (0..15)

    float acc[8][8];
#pragma unroll
    for (int i = 0; i < 8; i++)
#pragma unroll
        for (int j = 0; j < 8; j++) acc[i][j] = 0.0f;

    for (int k0 = 0; k0 < V; k0 += 32) {
        // A tile: 128 rows x 32 k. thread t loads row t (8 float4)
        {
            const float4* src = (const float4*)(x + (size_t)tid * V + k0);
#pragma unroll
            for (int q = 0; q < 8; q++) {
                float4 v = src[q];
                int k = q * 4;
                sA[k+0][tid] = v.x; sA[k+1][tid] = v.y;
                sA[k+2][tid] = v.z; sA[k+3][tid] = v.w;
            }
        }
        // B tile: 64 rows x 32 k. thread t: row t/2, half t%2 (4 float4)
        {
            int n    = tid >> 1;
            int half = (tid & 1) * 16;
            const float4* src = (const float4*)(W + (size_t)(n0 + n) * V + k0 + half);
#pragma unroll
            for (int q = 0; q < 4; q++) {
                float4 v = src[q];
                int k = half + q * 4;
                sB[k+0][n] = v.x; sB[k+1][n] = v.y;
                sB[k+2][n] = v.z; sB[k+3][n] = v.w;
            }
        }
        __syncthreads();
#pragma unroll
        for (int k = 0; k < 32; k++) {
            float a[8], b[8];
#pragma unroll
            for (int i = 0; i < 8; i++) a[i] = sA[k][ty * 8 + i];
#pragma unroll
            for (int j = 0; j < 8; j++) b[j] = sB[k][tx * 8 + j];
#pragma unroll
            for (int i = 0; i < 8; i++)
#pragma unroll
                for (int j = 0; j < 8; j++)
                    acc[i][j] = fmaf(a[i], b[j], acc[i][j]);
        }
        __syncthreads();
    }
    // epilogue: m = b*8 + t  ->  write g_xg[(t*16+b)*G4 + n] + bias
#pragma unroll
    for (int i = 0; i < 8; i++) {
        int m = ty * 8 + i;
        int b = m >> 3, t = m & 7;
        float* dst = g_xg + (size_t)(t * 16 + b) * G4;
#pragma unroll
        for (int j = 0; j < 8; j++) {
            int n = n0 + tx * 8 + j;
            dst[n] = acc[i][j] + bias[n];
        }
    }
}

// =====================================================================
// Shared mainloop for the M=16 recurrence/decoder matvec-GEMMs.
// Warp handles one j (columns j, V+j, 2V+j, 3V+j of W), lanes split K.
// Returns the 4 gate preactivation sums for b == lane (lanes 0..15).
// =====================================================================
struct Pre4 { float p0, p1, p2, p3; };

__device__ __forceinline__ Pre4 matvec_gates(
    const float* __restrict__ W, const float* __restrict__ hin,
    float (*sH)[KC], int j, int tid, int lane)
{
    float acc[16][4];
#pragma unroll
    for (int b = 0; b < 16; b++)
#pragma unroll
        for (int g = 0; g < 4; g++) acc[b][g] = 0.0f;

    for (int kc = 0; kc < V; kc += KC) {
        // cooperative stage of h chunk: 16 x KC floats = 1536 float4 / 256 thr
#pragma unroll
        for (int i = 0; i < (16 * KC / 4) / 256; i++) {
            int idx = tid + i * 256;
            int row = idx / (KC / 4);
            int col = idx % (KC / 4);
            float4 v = *(const float4*)(hin + (size_t)row * V + kc + col * 4);
            *(float4*)(&sH[row][col * 4]) = v;
        }
        __syncthreads();
#pragma unroll 1
        for (int kk = 0; kk < KC / 128; kk++) {
            int kloc = kk * 128 + lane * 4;
            int k    = kc + kloc;
            float4 w4[4];
#pragma unroll
            for (int g = 0; g < 4; g++)
                w4[g] = *(const float4*)(W + (size_t)(g * V + j) * V + k);
#pragma unroll
            for (int b = 0; b < 16; b++) {
                float4 h4 = *(const float4*)(&sH[b][kloc]);
#pragma unroll
                for (int g = 0; g < 4; g++) {
                    acc[b][g] = fmaf(h4.x, w4[g].x, acc[b][g]);
                    acc[b][g] = fmaf(h4.y, w4[g].y, acc[b][g]);
                    acc[b][g] = fmaf(h4.z, w4[g].z, acc[b][g]);
                    acc[b][g] = fmaf(h4.w, w4[g].w, acc[b][g]);
                }
            }
        }
        __syncthreads();
    }

    Pre4 r; r.p0 = r.p1 = r.p2 = r.p3 = 0.0f;
#pragma unroll
    for (int b = 0; b < 16; b++) {
        float s0 = acc[b][0], s1 = acc[b][1], s2 = acc[b][2], s3 = acc[b][3];
#pragma unroll
        for (int off = 16; off > 0; off >>= 1) {
            s0 += __shfl_xor_sync(0xffffffffu, s0, off);
            s1 += __shfl_xor_sync(0xffffffffu, s1, off);
            s2 += __shfl_xor_sync(0xffffffffu, s2, off);
            s3 += __shfl_xor_sync(0xffffffffu, s3, off);
        }
        if (lane == b) { r.p0 = s0; r.p1 = s1; r.p2 = s2; r.p3 = s3; }
    }
    return r;
}

// =====================================================================
// Encoder step t=0: h0 = c0 = 0 so gates come straight from g_xg[0].
// =====================================================================
__global__ void step0_kernel()
{
    int idx = blockIdx.x * blockDim.x + threadIdx.x;
    if (idx >= BSZ * V) return;
    int b = idx / V, j = idx % V;
    const float* xg = g_xg + (size_t)b * G4;  // t = 0
    float i_ = sigf(xg[j]);
    float gg = tanhf(xg[2 * V + j]);
    float o_ = sigf(xg[3 * V + j]);
    float c  = i_ * gg;               // f * c0 = 0
    g_c[idx]  = c;
    g_h0[idx] = o_ * tanhf(c);
}

// =====================================================================
// Encoder recurrence step t (1..7): gates = xg[t] + h_{t-1} @ W_hh^T
// =====================================================================
__global__ __launch_bounds__(256, 2) void rec_step_kernel(
    const float* __restrict__ Whh, int t)
{
    __shared__ float sH[16][KC];
    const int tid  = threadIdx.x;
    const int warp = tid >> 5;
    const int lane = tid & 31;
    const int j    = blockIdx.x * 8 + warp;

    const float* hin  = (t & 1) ? g_h0 : g_h1;   // h_{t-1}
    float*       hout = (t & 1) ? g_h1 : g_h0;   // h_t

    Pre4 p = matvec_gates(Whh, hin, sH, j, tid, lane);

    if (lane < 16) {
        int b = lane;
        const float* xg = g_xg + (size_t)(t * 16 + b) * G4;
        float i_ = sigf(p.p0 + xg[j]);
        float f_ = sigf(p.p1 + xg[V + j]);
        float gg = tanhf(p.p2 + xg[2 * V + j]);
        float o_ = sigf(p.p3 + xg[3 * V + j]);
        size_t o = (size_t)b * V + j;
        float c  = f_ * g_c[o] + i_ * gg;
        g_c[o]   = c;
        hout[o]  = o_ * tanhf(c);
    }
}

// =====================================================================
// enc_out[b] = dot(h_enc[b], fc_enc_w) + fc_enc_b    (writes d_out[0..15])
// =====================================================================
__global__ void fc_enc_kernel(const float* __restrict__ w,
                              const float* __restrict__ bias,
                              float* __restrict__ out)
{
    __shared__ float red[256];
    int b = blockIdx.x;
    const float* h = g_h1 + (size_t)b * V;   // h after t=7 lives in g_h1
    float s = 0.0f;
    for (int k = threadIdx.x; k < V; k += 256) s = fmaf(h[k], w[k], s);
    red[threadIdx.x] = s;
    __syncthreads();
    for (int st = 128; st > 0; st >>= 1) {
        if (threadIdx.x < st) red[threadIdx.x] += red[threadIdx.x + st];
        __syncthreads();
    }
    if (threadIdx.x == 0) out[b] = red[0] + bias[0];
}

// =====================================================================
// Decoder: gd = x_rev*W_ih_dec^T + h_enc@W_hh_dec^T + b_dec, gates,
// c_d = f*c_enc + i*g, h_d = o*tanh(c_d).  All TR steps independent.
// =====================================================================
__global__ __launch_bounds__(256, 2) void dec_gates_kernel(
    const float* __restrict__ Whh_dec, const float* __restrict__ b_dec,
    const float* __restrict__ W_ih_dec, const float* __restrict__ x_rev)
{
    __shared__ float sH[16][KC];
    const int tid  = threadIdx.x;
    const int warp = tid >> 5;
    const int lane = tid & 31;
    const int j    = blockIdx.x * 8 + warp;

    Pre4 p = matvec_gates(Whh_dec, g_h1, sH, j, tid, lane);

    if (lane < 16) {
        int b = lane;
        float bi = p.p0 + b_dec[j];
        float bf = p.p1 + b_dec[V + j];
        float bg = p.p2 + b_dec[2 * V + j];
        float bo = p.p3 + b_dec[3 * V + j];
        float w0 = W_ih_dec[j];
        float w1 = W_ih_dec[V + j];
        float w2 = W_ih_dec[2 * V + j];
        float w3 = W_ih_dec[3 * V + j];
        float ce = g_c[(size_t)b * V + j];
#pragma unroll
        for (int tr = 0; tr < TR; tr++) {
            float xr = x_rev[b * TR + tr];
            float i_ = sigf(bi + xr * w0);
            float f_ = sigf(bf + xr * w1);
            float gg = tanhf(bg + xr * w2);
            float o_ = sigf(bo + xr * w3);
            float cd = f_ * ce + i_ * gg;
            g_hd[(size_t)(b * TR + tr) * V + j] = o_ * tanhf(cd);
        }
    }
}

// =====================================================================
// K5: dec = h_d @ fc_dec_w^T + fc_dec_b, fused repeat(3) + output write.
// M=64, N=6912, K=6912.  BM=64, BN=64, BK=32, 64 threads, 8x8 micro.
// =====================================================================
__global__ __launch_bounds__(64) void gemm_dec_kernel(
    const float* __restrict__ Wfc, const float* __restrict__ bias,
    float* __restrict__ out)
{
    __shared__ float sA[32][68];
    __shared__ float sB[32][68];
    const int tid = threadIdx.x;
    const int n0  = blockIdx.x * 64;
    const int tx  = tid & 7;
    const int ty  = tid >> 3;

    float acc[8][8];
#pragma unroll
    for (int i = 0; i < 8; i++)
#pragma unroll
        for (int j = 0; j < 8; j++) acc[i][j] = 0.0f;

    for (int k0 = 0; k0 < V; k0 += 32) {
        {
            const float4* src = (const float4*)(g_hd + (size_t)tid * V + k0);
#pragma unroll
            for (int q = 0; q < 8; q++) {
                float4 v = src[q];
                int k = q * 4;
                sA[k+0][tid] = v.x; sA[k+1][tid] = v.y;
                sA[k+2][tid] = v.z; sA[k+3][tid] = v.w;
            }
        }
        {
            const float4* src = (const float4*)(Wfc + (size_t)(n0 + tid) * V + k0);
#pragma unroll
            for (int q = 0; q < 8; q++) {
                float4 v = src[q];
                int k = q * 4;
                sB[k+0][tid] = v.x; sB[k+1][tid] = v.y;
                sB[k+2][tid] = v.z; sB[k+3][tid] = v.w;
            }
        }
        __syncthreads();
#pragma unroll
        for (int k = 0; k < 32; k++) {
            float a[8], b[8];
#pragma unroll
            for (int i = 0; i < 8; i++) a[i] = sA[k][ty * 8 + i];
#pragma unroll
            for (int j = 0; j < 8; j++) b[j] = sB[k][tx * 8 + j];
#pragma unroll
            for (int i = 0; i < 8; i++)
#pragma unroll
                for (int j = 0; j < 8; j++)
                    acc[i][j] = fmaf(a[i], b[j], acc[i][j]);
        }
        __syncthreads();
    }
    // epilogue: row m = b*4 + tr ; out rows b*12 + tr*3 + {0,1,2}, offset 16
#pragma unroll
    for (int i = 0; i < 8; i++) {
        int m  = ty * 8 + i;
        int b  = m >> 2, tr = m & 3;
#pragma unroll
        for (int j = 0; j < 8; j++) {
            int n = n0 + tx * 8 + j;
            float val = acc[i][j] + bias[n];
            size_t base = 16 + (size_t)(b * 12 + tr * 3) * V + n;
            out[base]         = val;
            out[base + V]     = val;
            out[base + 2 * V] = val;
        }
    }
}

// =====================================================================
extern "C" void kernel_launch(void* const* d_in, const int* in_sizes, int n_in,
                              void* d_out, int out_size)
{
    (void)in_sizes; (void)n_in; (void)out_size;
    const float* x        = (const float*)d_in[0];
    const float* x_rev    = (const float*)d_in[1];
    const float* W_ih_enc = (const float*)d_in[2];
    const float* W_hh_enc = (const float*)d_in[3];
    const float* b_enc    = (const float*)d_in[4];
    const float* fc_enc_w = (const float*)d_in[5];
    const float* fc_enc_b = (const float*)d_in[6];
    const float* W_ih_dec = (const float*)d_in[7];
    const float* W_hh_dec = (const float*)d_in[8];
    const float* b_dec    = (const float*)d_in[9];
    const float* fc_dec_w = (const float*)d_in[10];
    const float* fc_dec_b = (const float*)d_in[11];
    float* out = (float*)d_out;

    // 1) xg = x @ W_ih_enc^T + b_enc  (all time steps at once)
    gemm_xg_kernel<<<G4 / 64, 128>>>(x, W_ih_enc, b_enc);

    // 2) encoder step 0 (h0 = 0 -> no W_hh pass needed)
    step0_kernel<<<(BSZ * V + 255) / 256, 256>>>();

    // 3) encoder steps 1..7 (serial dependence through h)
    for (int t = 1; t < TT; t++)
        rec_step_kernel<<<V / 8, 256>>>(W_hh_enc, t);

    // 4) enc_out -> d_out[0..15]
    fc_enc_kernel<<<BSZ, 256>>>(fc_enc_w, fc_enc_b, out);

    // 5) decoder gates (all TR steps, one W_hh_dec pass)
    dec_gates_kernel<<<V / 8, 256>>>(W_hh_dec, b_dec, W_ih_dec, x_rev);

    // 6) dec = h_d @ fc_dec_w^T + b, fused repeat(3) -> d_out[16..]
    gemm_dec_kernel<<<V / 64, 64>>>(fc_dec_w, fc_dec_b, out);
}

// round 3
// speedup vs baseline: 1.0565x; 1.0565x over previous
#include <cuda_runtime.h>
#include <cuda_bf16.h>
#include <mma.h>
#include <cstddef>

using namespace nvcuda;

#define V    6912
#define G4   27648   // 4*V
#define BSZ  16
#define TT   8
#define TR   4

// ---------------- device scratch (no allocation allowed) ----------------
__device__ float g_xg [128 * G4];      // [m=b*8+t][4V] x-gate preactivations (no bias)
__device__ float g_pre[BSZ * G4];      // [b][4V]  h @ W_hh^T  (no bias)
__device__ float g_h  [BSZ * V];       // encoder h_t
__device__ float g_c  [BSZ * V];       // encoder c_t
__device__ float g_hd [BSZ * TR * V];  // decoder h_d, row m = b*4+tr
__device__ float g_dec[BSZ * TR * V];  // decoder fc result (pre-bias)

__device__ __forceinline__ float sigf(float x) { return 1.0f / (1.0f + expf(-x)); }

// =====================================================================
// Generic tf32 tensor-core GEMM:  C[m][n] = sum_k A[m][k] * B[n][k]
//   A: [BM][V] fp32 row-major (lda = V)
//   B: [N][V]  fp32 row-major (ldb = V)  -> used as col-major k x n tiles
//   C: [BM][N] fp32 (ldc passed), pure store (bias folded into consumers)
// BN=128, BK=16, 256 threads, reg-staged global->smem double buffering.
// =====================================================================
template<int BM>
__global__ __launch_bounds__(256)
void gemm_tc(const float* __restrict__ A, const float* __restrict__ B,
             float* __restrict__ C, int ldc)
{
    constexpr int BN = 128, BK = 16, LDS = BK + 4;   // pad to 20 floats
    __shared__ float sA[BM][LDS];
    __shared__ float sB[BN][LDS];

    constexpr int WARPS_N = (BM == 128) ? 2 : (BM == 64) ? 4 : 8;
    constexpr int WARPS_M = 8 / WARPS_N;
    constexpr int WM = BM / WARPS_M;      // 32 / 32 / 16
    constexpr int WN = BN / WARPS_N;      // 64 / 32 / 16
    constexpr int MF = WM / 16, NF = WN / 16;

    const int tid = threadIdx.x;
    const int n0  = blockIdx.x * BN;
    const int w   = tid >> 5;
    const int wm  = w / WARPS_N;
    const int wn  = w % WARPS_N;

    wmma::fragment<wmma::accumulator, 16, 16, 8, float> acc[MF][NF];
#pragma unroll
    for (int i = 0; i < MF; i++)
#pragma unroll
        for (int j = 0; j < NF; j++) wmma::fill_fragment(acc[i][j], 0.0f);

    constexpr int A_F4 = BM * BK / 4;              // float4 loads for A tile
    constexpr int A_P  = (A_F4 + 255) / 256;
    float4 ar[A_P];
    float4 br[2];                                  // 128*16/4 = 512 -> 2 per thread

    auto load_g = [&](int k0) {
#pragma unroll
        for (int p = 0; p < A_P; p++) {
            int idx = tid + p * 256;
            if (A_F4 >= 256 * (p + 1) || idx < A_F4) {
                int m = idx >> 2, ks = idx & 3;
                ar[p] = *(const float4*)(A + (size_t)m * V + k0 + ks * 4);
            }
        }
#pragma unroll
        for (int p = 0; p < 2; p++) {
            int idx = tid + p * 256;
            int n = idx >> 2, ks = idx & 3;
            br[p] = *(const float4*)(B + (size_t)(n0 + n) * V + k0 + ks * 4);
        }
    };
    auto store_s = [&]() {
#pragma unroll
        for (int p = 0; p < A_P; p++) {
            int idx = tid + p * 256;
            if (A_F4 >= 256 * (p + 1) || idx < A_F4) {
                int m = idx >> 2, ks = idx & 3;
                *(float4*)&sA[m][ks * 4] = ar[p];
            }
        }
#pragma unroll
        for (int p = 0; p < 2; p++) {
            int idx = tid + p * 256;
            int n = idx >> 2, ks = idx & 3;
            *(float4*)&sB[n][ks * 4] = br[p];
        }
    };

    load_g(0);
    for (int k0 = 0; k0 < V; k0 += BK) {
        store_s();
        __syncthreads();
        if (k0 + BK < V) load_g(k0 + BK);
#pragma unroll
        for (int kk = 0; kk < BK; kk += 8) {
            wmma::fragment<wmma::matrix_a, 16, 16, 8, wmma::precision::tf32, wmma::row_major> af[MF];
            wmma::fragment<wmma::matrix_b, 16, 16, 8, wmma::precision::tf32, wmma::col_major> bfr[NF];
#pragma unroll
            for (int i = 0; i < MF; i++) {
                wmma::load_matrix_sync(af[i], &sA[wm * WM + i * 16][kk], LDS);
#pragma unroll
                for (int e = 0; e < af[i].num_elements; e++)
                    af[i].x[e] = wmma::__float_to_tf32(af[i].x[e]);
            }
#pragma unroll
            for (int j = 0; j < NF; j++) {
                wmma::load_matrix_sync(bfr[j], &sB[wn * WN + j * 16][kk], LDS);
#pragma unroll
                for (int e = 0; e < bfr[j].num_elements; e++)
                    bfr[j].x[e] = wmma::__float_to_tf32(bfr[j].x[e]);
            }
#pragma unroll
            for (int i = 0; i < MF; i++)
#pragma unroll
                for (int j = 0; j < NF; j++)
                    wmma::mma_sync(acc[i][j], af[i], bfr[j], acc[i][j]);
        }
        __syncthreads();
    }
#pragma unroll
    for (int i = 0; i < MF; i++)
#pragma unroll
        for (int j = 0; j < NF; j++)
            wmma::store_matrix_sync(
                C + (size_t)(wm * WM + i * 16) * ldc + n0 + wn * WN + j * 16,
                acc[i][j], ldc, wmma::mem_row_major);
}

// =====================================================================
// Encoder step t=0: h0 = c0 = 0 -> gates from g_xg row (b*8) + bias.
// =====================================================================
__global__ void step0_kernel(const float* __restrict__ be)
{
    int idx = blockIdx.x * blockDim.x + threadIdx.x;   // 16*V exactly
    int b = idx / V, j = idx - b * V;
    const float* xg = g_xg + (size_t)(b * 8) * G4;
    float i_ = sigf (xg[j]         + be[j]);
    float gg = tanhf(xg[2 * V + j] + be[2 * V + j]);
    float o_ = sigf (xg[3 * V + j] + be[3 * V + j]);
    float c  = i_ * gg;
    g_c[idx] = c;
    g_h[idx] = o_ * tanhf(c);
}

// =====================================================================
// Encoder recurrence pointwise, step t: gates = pre + xg[t] + bias.
// =====================================================================
__global__ void rec_point_kernel(int t, const float* __restrict__ be)
{
    int idx = blockIdx.x * blockDim.x + threadIdx.x;
    int b = idx / V, j = idx - b * V;
    const float* xg  = g_xg  + (size_t)(b * 8 + t) * G4;
    const float* pre = g_pre + (size_t)b * G4;
    float i_ = sigf (pre[j]         + xg[j]         + be[j]);
    float f_ = sigf (pre[V + j]     + xg[V + j]     + be[V + j]);
    float gg = tanhf(pre[2 * V + j] + xg[2 * V + j] + be[2 * V + j]);
    float o_ = sigf (pre[3 * V + j] + xg[3 * V + j] + be[3 * V + j]);
    float c  = f_ * g_c[idx] + i_ * gg;
    g_c[idx] = c;
    g_h[idx] = o_ * tanhf(c);
}

// =====================================================================
// enc_out[b] = dot(h_enc[b], fc_enc_w) + fc_enc_b  -> d_out[0..15]
// =====================================================================
__global__ void fc_enc_kernel(const float* __restrict__ wgt,
                              const float* __restrict__ bias,
                              float* __restrict__ out)
{
    __shared__ float red[256];
    int b = blockIdx.x;
    const float* h = g_h + (size_t)b * V;
    float s = 0.0f;
    for (int k = threadIdx.x; k < V; k += 256) s = fmaf(h[k], wgt[k], s);
    red[threadIdx.x] = s;
    __syncthreads();
    for (int st = 128; st > 0; st >>= 1) {
        if (threadIdx.x < st) red[threadIdx.x] += red[threadIdx.x + st];
        __syncthreads();
    }
    if (threadIdx.x == 0) out[b] = red[0] + bias[0];
}

// =====================================================================
// Decoder pointwise: gd = pre_d + b_dec + x_rev*W_ih_dec; all TR steps.
// =====================================================================
__global__ void dec_point_kernel(const float* __restrict__ bd,
                                 const float* __restrict__ Wid,
                                 const float* __restrict__ xrev)
{
    int idx = blockIdx.x * blockDim.x + threadIdx.x;
    int b = idx / V, j = idx - b * V;
    const float* pre = g_pre + (size_t)b * G4;
    float bi = pre[j]         + bd[j];
    float bf = pre[V + j]     + bd[V + j];
    float bg = pre[2 * V + j] + bd[2 * V + j];
    float bo = pre[3 * V + j] + bd[3 * V + j];
    float w0 = Wid[j], w1 = Wid[V + j], w2 = Wid[2 * V + j], w3 = Wid[3 * V + j];
    float ce = g_c[idx];
#pragma unroll
    for (int tr = 0; tr < TR; tr++) {
        float xr = xrev[b * TR + tr];
        float i_ = sigf (bi + xr * w0);
        float f_ = sigf (bf + xr * w1);
        float gg = tanhf(bg + xr * w2);
        float o_ = sigf (bo + xr * w3);
        float cd = f_ * ce + i_ * gg;
        g_hd[(size_t)(b * TR + tr) * V + j] = o_ * tanhf(cd);
    }
}

// =====================================================================
// Output scatter: out rows 16 + (b*12 + tr*3 + {0,1,2})*V  = g_dec + bias
// =====================================================================
__global__ void dec_out_kernel(const float* __restrict__ fcb,
                               float* __restrict__ out)
{
    int idx = blockIdx.x * blockDim.x + threadIdx.x;   // 64*V exactly
    int m = idx / V, n = idx - m * V;
    float val = g_dec[idx] + fcb[n];
    int b = m >> 2, tr = m & 3;
    size_t base = 16 + (size_t)(b * 12 + tr * 3) * V + n;
    out[base]         = val;
    out[base + V]     = val;
    out[base + 2 * V] = val;
}

// =====================================================================
extern "C" void kernel_launch(void* const* d_in, const int* in_sizes, int n_in,
                              void* d_out, int out_size)
{
    (void)in_sizes; (void)n_in; (void)out_size;
    const float* x        = (const float*)d_in[0];
    const float* x_rev    = (const float*)d_in[1];
    const float* W_ih_enc = (const float*)d_in[2];
    const float* W_hh_enc = (const float*)d_in[3];
    const float* b_enc    = (const float*)d_in[4];
    const float* fc_enc_w = (const float*)d_in[5];
    const float* fc_enc_b = (const float*)d_in[6];
    const float* W_ih_dec = (const float*)d_in[7];
    const float* W_hh_dec = (const float*)d_in[8];
    const float* b_dec    = (const float*)d_in[9];
    const float* fc_dec_w = (const float*)d_in[10];
    const float* fc_dec_b = (const float*)d_in[11];
    float* out = (float*)d_out;

    float* xg_p  = nullptr; cudaGetSymbolAddress((void**)&xg_p,  g_xg);
    float* pre_p = nullptr; cudaGetSymbolAddress((void**)&pre_p, g_pre);
    float* h_p   = nullptr; cudaGetSymbolAddress((void**)&h_p,   g_h);
    float* hd_p  = nullptr; cudaGetSymbolAddress((void**)&hd_p,  g_hd);
    float* dec_p = nullptr; cudaGetSymbolAddress((void**)&dec_p, g_dec);

    // 1) xg = x @ W_ih_enc^T  (rows m = b*8+t), tf32 tensor cores
    gemm_tc<128><<<G4 / 128, 256>>>(x, W_ih_enc, xg_p, G4);

    // 2) encoder step 0 (h0 = 0 -> no W_hh pass)
    step0_kernel<<<BSZ * V / 256, 256>>>(b_enc);

    // 3) encoder steps 1..7: GEMM (h @ W_hh^T) + pointwise gates
    for (int t = 1; t < TT; t++) {
        gemm_tc<16><<<G4 / 128, 256>>>(h_p, W_hh_enc, pre_p, G4);
        rec_point_kernel<<<BSZ * V / 256, 256>>>(t, b_enc);
    }

    // 4) enc_out -> d_out[0..15]
    fc_enc_kernel<<<BSZ, 256>>>(fc_enc_w, fc_enc_b, out);

    // 5) decoder pre = h_enc @ W_hh_dec^T, then gates (all TR steps)
    gemm_tc<16><<<G4 / 128, 256>>>(h_p, W_hh_dec, pre_p, G4);
    dec_point_kernel<<<BSZ * V / 256, 256>>>(b_dec, W_ih_dec, x_rev);

    // 6) dec = h_d @ fc_dec_w^T, then bias + repeat(3) scatter
    gemm_tc<64><<<V / 128, 256>>>(hd_p, fc_dec_w, dec_p, V);
    dec_out_kernel<<<BSZ * TR * V / 256, 256>>>(fc_dec_b, out);
}

// round 4
// speedup vs baseline: 3.3817x; 3.2009x over previous
#include <cuda_runtime.h>
#include <cuda_fp16.h>
#include <mma.h>
#include <cstddef>
#include <cstdint>

using namespace nvcuda;

#define V    6912
#define G4   27648   // 4*V
#define BSZ  16
#define TT   8
#define TR   4
#define BN   128

// ---------------- device scratch (no allocation allowed) ----------------
__device__ __half g_whh16[(size_t)G4 * V];   // fp16 copy of W_hh_enc (382MB)
__device__ __half g_x16 [128 * V];           // x converted to fp16
__device__ __half g_h16 [BSZ * V];           // encoder h (fp16, GEMM A)
__device__ __half g_hd16[BSZ * TR * V];      // decoder h_d (fp16, GEMM A)
__device__ float  g_h   [BSZ * V];           // encoder h (fp32, fc_enc)
__device__ float  g_c   [BSZ * V];
__device__ float  g_xgK [2][128 * G4];       // xg partials (K-split 2)
__device__ float  g_preK[4][BSZ * G4];       // h@Whh^T partials (K-split 4)
__device__ float  g_decK[4][BSZ * TR * V];   // fc_dec partials (K-split 4)

__device__ __forceinline__ float sigf(float x) { return 1.0f / (1.0f + expf(-x)); }

// pack 8 consecutive floats (two float4) into 8 halfs (one uint4)
__device__ __forceinline__ uint4 pack8(float4 a, float4 b)
{
    __half2 h0 = __floats2half2_rn(a.x, a.y);
    __half2 h1 = __floats2half2_rn(a.z, a.w);
    __half2 h2 = __floats2half2_rn(b.x, b.y);
    __half2 h3 = __floats2half2_rn(b.z, b.w);
    uint4 u;
    u.x = *reinterpret_cast<unsigned*>(&h0);
    u.y = *reinterpret_cast<unsigned*>(&h1);
    u.z = *reinterpret_cast<unsigned*>(&h2);
    u.w = *reinterpret_cast<unsigned*>(&h3);
    return u;
}

// =====================================================================
// fp32 -> fp16 stream converter (8 elements / thread)
// =====================================================================
__global__ void conv16_kernel(const float* __restrict__ src,
                              __half* __restrict__ dst, int n8)
{
    int idx = blockIdx.x * 256 + threadIdx.x;
    if (idx >= n8) return;
    const float4* s = (const float4*)src + (size_t)idx * 2;
    ((uint4*)dst)[idx] = pack8(s[0], s[1]);
}

// =====================================================================
// Unified fp16-MMA GEMM:  Cp[y][m][n] = sum_{k in slice y} A[m][k]*B[n][k]
//   A: fp16 [BM][V] row-major.  B: [N][V] row-major, fp16 (WHALF) or fp32
//   (converted to fp16 in-register while staging to smem).
//   grid.x = N/BN, grid.y = KSPLIT (k-slice).  Pure store epilogue.
// =====================================================================
template<int BM, int BK, bool WHALF>
__global__ __launch_bounds__(256)
void gemm16(const __half* __restrict__ A, const void* __restrict__ Bv,
            float* __restrict__ Cp, int N, int klen)
{
    constexpr int LDS = BK + 8;                 // half units; 16B-aligned rows
    __shared__ __half sA[2][BM][LDS];
    __shared__ __half sB[2][BN][LDS];

    const __half* Bh = (const __half*)Bv;
    const float*  Bf = (const float*)Bv;

    const int tid   = threadIdx.x;
    const int n0    = blockIdx.x * BN;
    const int kbase = blockIdx.y * klen;
    const int niter = klen / BK;

    constexpr int WARPS_M = (BM <= 16) ? 1 : 2;
    constexpr int WARPS_N = 8 / WARPS_M;
    constexpr int WM = BM / WARPS_M, WN = BN / WARPS_N;
    constexpr int MF = WM / 16, NF = WN / 16;
    const int w  = tid >> 5;
    const int wm = w / WARPS_N, wn = w % WARPS_N;

    wmma::fragment<wmma::accumulator, 16, 16, 16, float> acc[MF][NF];
#pragma unroll
    for (int i = 0; i < MF; i++)
#pragma unroll
        for (int j = 0; j < NF; j++) wmma::fill_fragment(acc[i][j], 0.0f);

    constexpr int CPR   = BK / 8;               // 16B chunks per row
    constexpr int BCH   = BN * CPR / 256;       // B chunks per thread
    constexpr int ACH_T = BM * CPR;             // total A chunks
    constexpr int ACH   = (ACH_T + 255) / 256;

    uint4 rb[BCH], ra[ACH];

    auto load = [&](int k0) {
#pragma unroll
        for (int p = 0; p < BCH; p++) {
            int c = tid + p * 256;
            int row = c / CPR, kc = (c % CPR) * 8;
            if constexpr (WHALF) {
                rb[p] = *(const uint4*)(Bh + (size_t)(n0 + row) * V + k0 + kc);
            } else {
                const float* s = Bf + (size_t)(n0 + row) * V + k0 + kc;
                rb[p] = pack8(*(const float4*)s, *(const float4*)(s + 4));
            }
        }
#pragma unroll
        for (int p = 0; p < ACH; p++) {
            int c = tid + p * 256;
            if (ACH_T >= (p + 1) * 256 || c < ACH_T) {
                int row = c / CPR, kc = (c % CPR) * 8;
                ra[p] = *(const uint4*)(A + (size_t)row * V + k0 + kc);
            }
        }
    };
    auto store = [&](int buf) {
#pragma unroll
        for (int p = 0; p < BCH; p++) {
            int c = tid + p * 256;
            int row = c / CPR, kc = (c % CPR) * 8;
            *(uint4*)(&sB[buf][row][kc]) = rb[p];
        }
#pragma unroll
        for (int p = 0; p < ACH; p++) {
            int c = tid + p * 256;
            if (ACH_T >= (p + 1) * 256 || c < ACH_T) {
                int row = c / CPR, kc = (c % CPR) * 8;
                *(uint4*)(&sA[buf][row][kc]) = ra[p];
            }
        }
    };

    load(kbase);
    store(0);
    if (niter > 1) load(kbase + BK);
    __syncthreads();

    for (int i = 0; i < niter; i++) {
        int p = i & 1;
        if (i + 1 < niter) store(p ^ 1);            // stage chunk i+1
        if (i + 2 < niter) load(kbase + (i + 2) * BK);  // prefetch i+2
#pragma unroll
        for (int kk = 0; kk < BK; kk += 16) {
            wmma::fragment<wmma::matrix_a, 16, 16, 16, __half, wmma::row_major> af[MF];
            wmma::fragment<wmma::matrix_b, 16, 16, 16, __half, wmma::col_major> bf[NF];
#pragma unroll
            for (int i_ = 0; i_ < MF; i_++)
                wmma::load_matrix_sync(af[i_], &sA[p][wm * WM + i_ * 16][kk], LDS);
#pragma unroll
            for (int j_ = 0; j_ < NF; j_++)
                wmma::load_matrix_sync(bf[j_], &sB[p][wn * WN + j_ * 16][kk], LDS);
#pragma unroll
            for (int i_ = 0; i_ < MF; i_++)
#pragma unroll
                for (int j_ = 0; j_ < NF; j_++)
                    wmma::mma_sync(acc[i_][j_], af[i_], bf[j_], acc[i_][j_]);
        }
        __syncthreads();
    }

    float* cbase = Cp + (size_t)blockIdx.y * BM * N;
#pragma unroll
    for (int i_ = 0; i_ < MF; i_++)
#pragma unroll
        for (int j_ = 0; j_ < NF; j_++)
            wmma::store_matrix_sync(
                cbase + (size_t)(wm * WM + i_ * 16) * N + n0 + wn * WN + j_ * 16,
                acc[i_][j_], N, wmma::mem_row_major);
}

// =====================================================================
// Encoder step t=0: h0 = c0 = 0 -> gates from xg (2 slices) + bias.
// =====================================================================
__global__ void step0_kernel(const float* __restrict__ be)
{
    int idx = blockIdx.x * blockDim.x + threadIdx.x;   // 16*V exactly
    int b = idx / V, j = idx - b * V;
    size_t r = (size_t)(b * 8) * G4;
    const float* x0 = g_xgK[0] + r;
    const float* x1 = g_xgK[1] + r;
    float i_ = sigf (x0[j]         + x1[j]         + be[j]);
    float gg = tanhf(x0[2 * V + j] + x1[2 * V + j] + be[2 * V + j]);
    float o_ = sigf (x0[3 * V + j] + x1[3 * V + j] + be[3 * V + j]);
    float c  = i_ * gg;
    g_c[idx] = c;
    float h  = o_ * tanhf(c);
    g_h[idx]   = h;
    g_h16[idx] = __float2half(h);
}

// =====================================================================
// Encoder recurrence pointwise: gates = sum(preK) + sum(xgK) + bias.
// =====================================================================
__global__ void rec_point_kernel(int t, const float* __restrict__ be)
{
    int idx = blockIdx.x * blockDim.x + threadIdx.x;
    int b = idx / V, j = idx - b * V;
    size_t rx = (size_t)(b * 8 + t) * G4;
    size_t rp = (size_t)b * G4;
    float pi = be[j], pf = be[V + j], pg = be[2 * V + j], po = be[3 * V + j];
#pragma unroll
    for (int s = 0; s < 2; s++) {
        const float* x = g_xgK[s] + rx;
        pi += x[j]; pf += x[V + j]; pg += x[2 * V + j]; po += x[3 * V + j];
    }
#pragma unroll
    for (int s = 0; s < 4; s++) {
        const float* p = g_preK[s] + rp;
        pi += p[j]; pf += p[V + j]; pg += p[2 * V + j]; po += p[3 * V + j];
    }
    float i_ = sigf(pi), f_ = sigf(pf), gg = tanhf(pg), o_ = sigf(po);
    float c  = f_ * g_c[idx] + i_ * gg;
    g_c[idx] = c;
    float h  = o_ * tanhf(c);
    g_h[idx]   = h;
    g_h16[idx] = __float2half(h);
}

// =====================================================================
// enc_out[b] = dot(h_enc[b], fc_enc_w) + fc_enc_b  -> d_out[0..15]
// =====================================================================
__global__ void fc_enc_kernel(const float* __restrict__ wgt,
                              const float* __restrict__ bias,
                              float* __restrict__ out)
{
    __shared__ float red[256];
    int b = blockIdx.x;
    const float* h = g_h + (size_t)b * V;
    float s = 0.0f;
    for (int k = threadIdx.x; k < V; k += 256) s = fmaf(h[k], wgt[k], s);
    red[threadIdx.x] = s;
    __syncthreads();
    for (int st = 128; st > 0; st >>= 1) {
        if (threadIdx.x < st) red[threadIdx.x] += red[threadIdx.x + st];
        __syncthreads();
    }
    if (threadIdx.x == 0) out[b] = red[0] + bias[0];
}

// =====================================================================
// Decoder pointwise: all TR steps from one h@Whh_dec^T (4 slices).
// =====================================================================
__global__ void dec_point_kernel(const float* __restrict__ bd,
                                 const float* __restrict__ Wid,
                                 const float* __restrict__ xrev)
{
    int idx = blockIdx.x * blockDim.x + threadIdx.x;
    int b = idx / V, j = idx - b * V;
    size_t rp = (size_t)b * G4;
    float bi = bd[j], bf = bd[V + j], bg = bd[2 * V + j], bo = bd[3 * V + j];
#pragma unroll
    for (int s = 0; s < 4; s++) {
        const float* p = g_preK[s] + rp;
        bi += p[j]; bf += p[V + j]; bg += p[2 * V + j]; bo += p[3 * V + j];
    }
    float w0 = Wid[j], w1 = Wid[V + j], w2 = Wid[2 * V + j], w3 = Wid[3 * V + j];
    float ce = g_c[idx];
#pragma unroll
    for (int tr = 0; tr < TR; tr++) {
        float xr = xrev[b * TR + tr];
        float i_ = sigf (bi + xr * w0);
        float f_ = sigf (bf + xr * w1);
        float gg = tanhf(bg + xr * w2);
        float o_ = sigf (bo + xr * w3);
        float cd = f_ * ce + i_ * gg;
        g_hd16[(size_t)(b * TR + tr) * V + j] = __float2half(o_ * tanhf(cd));
    }
}

// =====================================================================
// Output scatter: sum 4 fc_dec slices + bias, repeat(3) write.
// =====================================================================
__global__ void dec_out_kernel(const float* __restrict__ fcb,
                               float* __restrict__ out)
{
    int idx = blockIdx.x * blockDim.x + threadIdx.x;   // 64*V exactly
    int m = idx / V, n = idx - m * V;
    float val = g_decK[0][idx] + g_decK[1][idx] + g_decK[2][idx]
              + g_decK[3][idx] + fcb[n];
    int b = m >> 2, tr = m & 3;
    size_t base = 16 + (size_t)(b * 12 + tr * 3) * V + n;
    out[base]         = val;
    out[base + V]     = val;
    out[base + 2 * V] = val;
}

// =====================================================================
extern "C" void kernel_launch(void* const* d_in, const int* in_sizes, int n_in,
                              void* d_out, int out_size)
{
    (void)in_sizes; (void)n_in; (void)out_size;
    const float* x        = (const float*)d_in[0];
    const float* x_rev    = (const float*)d_in[1];
    const float* W_ih_enc = (const float*)d_in[2];
    const float* W_hh_enc = (const float*)d_in[3];
    const float* b_enc    = (const float*)d_in[4];
    const float* fc_enc_w = (const float*)d_in[5];
    const float* fc_enc_b = (const float*)d_in[6];
    const float* W_ih_dec = (const float*)d_in[7];
    const float* W_hh_dec = (const float*)d_in[8];
    const float* b_dec    = (const float*)d_in[9];
    const float* fc_dec_w = (const float*)d_in[10];
    const float* fc_dec_b = (const float*)d_in[11];
    float* out = (float*)d_out;

    __half *whh16_p, *x16_p, *h16_p, *hd16_p;
    float  *xgK_p, *preK_p, *decK_p;
    cudaGetSymbolAddress((void**)&whh16_p, g_whh16);
    cudaGetSymbolAddress((void**)&x16_p,   g_x16);
    cudaGetSymbolAddress((void**)&h16_p,   g_h16);
    cudaGetSymbolAddress((void**)&hd16_p,  g_hd16);
    cudaGetSymbolAddress((void**)&xgK_p,   g_xgK);
    cudaGetSymbolAddress((void**)&preK_p,  g_preK);
    cudaGetSymbolAddress((void**)&decK_p,  g_decK);

    // 0) conversions: x -> fp16, W_hh_enc -> fp16 (amortized over 7 steps)
    conv16_kernel<<<(128 * V / 8 + 255) / 256, 256>>>(x, x16_p, 128 * V / 8);
    {
        int n8 = (int)((size_t)G4 * V / 8);
        conv16_kernel<<<(n8 + 255) / 256, 256>>>(W_hh_enc, whh16_p, n8);
    }

    // 1) xg = x @ W_ih_enc^T  (fp32 W converted in-register), K-split 2
    gemm16<128, 32, false><<<dim3(G4 / BN, 2), 256>>>(x16_p, W_ih_enc, xgK_p, G4, V / 2);

    // 2) encoder step 0
    step0_kernel<<<BSZ * V / 256, 256>>>(b_enc);

    // 3) encoder steps 1..7: fp16-weight GEMM + pointwise gates
    for (int t = 1; t < TT; t++) {
        gemm16<16, 64, true><<<dim3(G4 / BN, 4), 256>>>(h16_p, whh16_p, preK_p, G4, V / 4);
        rec_point_kernel<<<BSZ * V / 256, 256>>>(t, b_enc);
    }

    // 4) enc_out -> d_out[0..15]
    fc_enc_kernel<<<BSZ, 256>>>(fc_enc_w, fc_enc_b, out);

    // 5) decoder pre = h_enc @ W_hh_dec^T (fp32 W, single use), then gates
    gemm16<16, 64, false><<<dim3(G4 / BN, 4), 256>>>(h16_p, W_hh_dec, preK_p, G4, V / 4);
    dec_point_kernel<<<BSZ * V / 256, 256>>>(b_dec, W_ih_dec, x_rev);

    // 6) dec = h_d @ fc_dec_w^T (fp32 W), then bias + repeat(3) scatter
    gemm16<64, 32, false><<<dim3(V / BN, 4), 256>>>(hd16_p, fc_dec_w, decK_p, V, V / 4);
    dec_out_kernel<<<BSZ * TR * V / 256, 256>>>(fc_dec_b, out);
}

// round 5
// speedup vs baseline: 3.6634x; 1.0833x over previous
#include <cuda_runtime.h>
#include <cuda_fp16.h>
#include <mma.h>
#include <cstddef>
#include <cstdint>

using namespace nvcuda;

#define V    6912
#define G4   27648   // 4*V
#define BSZ  16
#define TT   8
#define TR   4
#define BN   128

// ---------------- device scratch (no allocation allowed) ----------------
__device__ __half g_whh16[(size_t)G4 * V];   // fp16 W_hh_enc (written by step-1 GEMM)
__device__ __half g_x16 [128 * V];           // x converted to fp16
__device__ __half g_h16 [BSZ * V];           // encoder h (fp16, GEMM A)
__device__ __half g_hd16[BSZ * TR * V];      // decoder h_d (fp16, GEMM A)
__device__ float  g_h   [BSZ * V];           // encoder h (fp32, fc_enc)
__device__ float  g_c   [BSZ * V];
__device__ float  g_xgK [2][128 * G4];       // xg partials (K-split 2)
__device__ float  g_preK[8][BSZ * G4];       // h@Whh^T partials (K-split up to 8)
__device__ float  g_decK[4][BSZ * TR * V];   // fc_dec partials (K-split 4)

__device__ __forceinline__ float sigf(float x) { return 1.0f / (1.0f + expf(-x)); }

__device__ __forceinline__ uint4 pack8(float4 a, float4 b)
{
    __half2 h0 = __floats2half2_rn(a.x, a.y);
    __half2 h1 = __floats2half2_rn(a.z, a.w);
    __half2 h2 = __floats2half2_rn(b.x, b.y);
    __half2 h3 = __floats2half2_rn(b.z, b.w);
    uint4 u;
    u.x = *reinterpret_cast<unsigned*>(&h0);
    u.y = *reinterpret_cast<unsigned*>(&h1);
    u.z = *reinterpret_cast<unsigned*>(&h2);
    u.w = *reinterpret_cast<unsigned*>(&h3);
    return u;
}

// =====================================================================
// fp32 -> fp16 stream converter (8 elements / thread) — used for x only
// =====================================================================
__global__ void conv16_kernel(const float* __restrict__ src,
                              __half* __restrict__ dst, int n8)
{
    int idx = blockIdx.x * 256 + threadIdx.x;
    if (idx >= n8) return;
    const float4* s = (const float4*)src + (size_t)idx * 2;
    ((uint4*)dst)[idx] = pack8(s[0], s[1]);
}

// =====================================================================
// Register-staged fp16-MMA GEMM (for fp32-weight single-pass GEMMs).
//   Cp[y][m][n] = sum_{k slice y} A[m][k]*B[n][k]
//   WHALF: B already fp16.  WRITEB: also store converted fp16 B to Bout.
// =====================================================================
template<int BM, int BK, bool WHALF, bool WRITEB>
__global__ __launch_bounds__(256)
void gemm16(const __half* __restrict__ A, const void* __restrict__ Bv,
            float* __restrict__ Cp, int N, int klen, __half* __restrict__ Bout)
{
    constexpr int LDS = BK + 8;
    __shared__ __half sA[2][BM][LDS];
    __shared__ __half sB[2][BN][LDS];

    const __half* Bh = (const __half*)Bv;
    const float*  Bf = (const float*)Bv;

    const int tid   = threadIdx.x;
    const int n0    = blockIdx.x * BN;
    const int kbase = blockIdx.y * klen;
    const int niter = klen / BK;

    constexpr int WARPS_M = (BM <= 16) ? 1 : 2;
    constexpr int WARPS_N = 8 / WARPS_M;
    constexpr int WM = BM / WARPS_M, WN = BN / WARPS_N;
    constexpr int MF = WM / 16, NF = WN / 16;
    const int w  = tid >> 5;
    const int wm = w / WARPS_N, wn = w % WARPS_N;

    wmma::fragment<wmma::accumulator, 16, 16, 16, float> acc[MF][NF];
#pragma unroll
    for (int i = 0; i < MF; i++)
#pragma unroll
        for (int j = 0; j < NF; j++) wmma::fill_fragment(acc[i][j], 0.0f);

    constexpr int CPR   = BK / 8;
    constexpr int BCH   = BN * CPR / 256;
    constexpr int ACH_T = BM * CPR;
    constexpr int ACH   = (ACH_T + 255) / 256;

    uint4 rb[BCH], ra[ACH];

    auto load = [&](int k0) {
#pragma unroll
        for (int p = 0; p < BCH; p++) {
            int c = tid + p * 256;
            int row = c / CPR, kc = (c % CPR) * 8;
            if constexpr (WHALF) {
                rb[p] = *(const uint4*)(Bh + (size_t)(n0 + row) * V + k0 + kc);
            } else {
                const float* s = Bf + (size_t)(n0 + row) * V + k0 + kc;
                rb[p] = pack8(*(const float4*)s, *(const float4*)(s + 4));
                if constexpr (WRITEB)
                    *(uint4*)(Bout + (size_t)(n0 + row) * V + k0 + kc) = rb[p];
            }
        }
#pragma unroll
        for (int p = 0; p < ACH; p++) {
            int c = tid + p * 256;
            if (ACH_T >= (p + 1) * 256 || c < ACH_T) {
                int row = c / CPR, kc = (c % CPR) * 8;
                ra[p] = *(const uint4*)(A + (size_t)row * V + k0 + kc);
            }
        }
    };
    auto store = [&](int buf) {
#pragma unroll
        for (int p = 0; p < BCH; p++) {
            int c = tid + p * 256;
            int row = c / CPR, kc = (c % CPR) * 8;
            *(uint4*)(&sB[buf][row][kc]) = rb[p];
        }
#pragma unroll
        for (int p = 0; p < ACH; p++) {
            int c = tid + p * 256;
            if (ACH_T >= (p + 1) * 256 || c < ACH_T) {
                int row = c / CPR, kc = (c % CPR) * 8;
                *(uint4*)(&sA[buf][row][kc]) = ra[p];
            }
        }
    };

    load(kbase);
    store(0);
    if (niter > 1) load(kbase + BK);
    __syncthreads();

    for (int i = 0; i < niter; i++) {
        int p = i & 1;
        if (i + 1 < niter) store(p ^ 1);
        if (i + 2 < niter) load(kbase + (i + 2) * BK);
#pragma unroll
        for (int kk = 0; kk < BK; kk += 16) {
            wmma::fragment<wmma::matrix_a, 16, 16, 16, __half, wmma::row_major> af[MF];
            wmma::fragment<wmma::matrix_b, 16, 16, 16, __half, wmma::col_major> bf[NF];
#pragma unroll
            for (int i_ = 0; i_ < MF; i_++)
                wmma::load_matrix_sync(af[i_], &sA[p][wm * WM + i_ * 16][kk], LDS);
#pragma unroll
            for (int j_ = 0; j_ < NF; j_++)
                wmma::load_matrix_sync(bf[j_], &sB[p][wn * WN + j_ * 16][kk], LDS);
#pragma unroll
            for (int i_ = 0; i_ < MF; i_++)
#pragma unroll
                for (int j_ = 0; j_ < NF; j_++)
                    wmma::mma_sync(acc[i_][j_], af[i_], bf[j_], acc[i_][j_]);
        }
        __syncthreads();
    }

    float* cbase = Cp + (size_t)blockIdx.y * BM * N;
#pragma unroll
    for (int i_ = 0; i_ < MF; i_++)
#pragma unroll
        for (int j_ = 0; j_ < NF; j_++)
            wmma::store_matrix_sync(
                cbase + (size_t)(wm * WM + i_ * 16) * N + n0 + wn * WN + j_ * 16,
                acc[i_][j_], N, wmma::mem_row_major);
}

// =====================================================================
// cp.async-pipelined fp16 GEMM, BM=16 (recurrence bulk, steps 2..7).
//   4 stages x BK=32, 8 warps each own one 16-wide N fragment.
// =====================================================================
template<int BK, int STAGES>
__global__ __launch_bounds__(256)
void gemm16_ca(const __half* __restrict__ A, const __half* __restrict__ B,
               float* __restrict__ Cp, int N, int klen)
{
    constexpr int BM  = 16;
    constexpr int LDS = BK + 8;
    __shared__ __half sA[STAGES][BM][LDS];
    __shared__ __half sB[STAGES][BN][LDS];

    const int tid   = threadIdx.x;
    const int n0    = blockIdx.x * BN;
    const int kbase = blockIdx.y * klen;
    const int niter = klen / BK;
    const int w     = tid >> 5;

    wmma::fragment<wmma::accumulator, 16, 16, 16, float> acc;
    wmma::fill_fragment(acc, 0.0f);

    constexpr int CPR   = BK / 8;          // 16B chunks per row
    constexpr int BCH   = BN * CPR / 256;  // per-thread B chunks
    constexpr int ACH_T = BM * CPR;        // total A chunks (<=256)

    auto stage = [&](int s, int k0) {
#pragma unroll
        for (int p = 0; p < BCH; p++) {
            int c = tid + p * 256;
            int row = c / CPR, kc = (c % CPR) * 8;
            uint32_t d = (uint32_t)__cvta_generic_to_shared(&sB[s][row][kc]);
            const void* g = B + (size_t)(n0 + row) * V + k0 + kc;
            asm volatile("cp.async.cg.shared.global [%0], [%1], 16;\n" :: "r"(d), "l"(g));
        }
        if (tid < ACH_T) {
            int row = tid / CPR, kc = (tid % CPR) * 8;
            uint32_t d = (uint32_t)__cvta_generic_to_shared(&sA[s][row][kc]);
            const void* g = A + (size_t)row * V + k0 + kc;
            asm volatile("cp.async.cg.shared.global [%0], [%1], 16;\n" :: "r"(d), "l"(g));
        }
        asm volatile("cp.async.commit_group;\n");
    };

    int issued = 0;
    for (; issued < STAGES - 1 && issued < niter; issued++)
        stage(issued, kbase + issued * BK);

    for (int i = 0; i < niter; i++) {
        if (issued < niter) { stage(issued % STAGES, kbase + issued * BK); issued++; }
        else                { asm volatile("cp.async.commit_group;\n"); }
        asm volatile("cp.async.wait_group %0;\n" :: "n"(STAGES - 1));
        __syncthreads();
        int s = i % STAGES;
#pragma unroll
        for (int kk = 0; kk < BK; kk += 16) {
            wmma::fragment<wmma::matrix_a, 16, 16, 16, __half, wmma::row_major> af;
            wmma::fragment<wmma::matrix_b, 16, 16, 16, __half, wmma::col_major> bf;
            wmma::load_matrix_sync(af, &sA[s][0][kk], LDS);
            wmma::load_matrix_sync(bf, &sB[s][w * 16][kk], LDS);
            wmma::mma_sync(acc, af, bf, acc);
        }
        __syncthreads();
    }

    float* cb = Cp + (size_t)blockIdx.y * BM * N;
    wmma::store_matrix_sync(cb + n0 + w * 16, acc, N, wmma::mem_row_major);
}

// =====================================================================
// Encoder step t=0: h0 = c0 = 0 -> gates from xg (2 slices) + bias.
// =====================================================================
__global__ void step0_kernel(const float* __restrict__ be)
{
    int idx = blockIdx.x * blockDim.x + threadIdx.x;   // 16*V exactly
    int b = idx / V, j = idx - b * V;
    size_t r = (size_t)(b * 8) * G4;
    const float* x0 = g_xgK[0] + r;
    const float* x1 = g_xgK[1] + r;
    float i_ = sigf (x0[j]         + x1[j]         + be[j]);
    float gg = tanhf(x0[2 * V + j] + x1[2 * V + j] + be[2 * V + j]);
    float o_ = sigf (x0[3 * V + j] + x1[3 * V + j] + be[3 * V + j]);
    float c  = i_ * gg;
    g_c[idx] = c;
    float h  = o_ * tanhf(c);
    g_h[idx]   = h;
    g_h16[idx] = __float2half(h);
}

// =====================================================================
// Encoder recurrence pointwise: gates = sum(preK[0..nsl)) + xg + bias.
// =====================================================================
__global__ void rec_point_kernel(int t, const float* __restrict__ be, int nsl)
{
    int idx = blockIdx.x * blockDim.x + threadIdx.x;
    int b = idx / V, j = idx - b * V;
    size_t rx = (size_t)(b * 8 + t) * G4;
    size_t rp = (size_t)b * G4;
    float pi = be[j], pf = be[V + j], pg = be[2 * V + j], po = be[3 * V + j];
#pragma unroll
    for (int s = 0; s < 2; s++) {
        const float* x = g_xgK[s] + rx;
        pi += x[j]; pf += x[V + j]; pg += x[2 * V + j]; po += x[3 * V + j];
    }
    for (int s = 0; s < nsl; s++) {
        const float* p = g_preK[s] + rp;
        pi += p[j]; pf += p[V + j]; pg += p[2 * V + j]; po += p[3 * V + j];
    }
    float i_ = sigf(pi), f_ = sigf(pf), gg = tanhf(pg), o_ = sigf(po);
    float c  = f_ * g_c[idx] + i_ * gg;
    g_c[idx] = c;
    float h  = o_ * tanhf(c);
    g_h[idx]   = h;
    g_h16[idx] = __float2half(h);
}

// =====================================================================
__global__ void fc_enc_kernel(const float* __restrict__ wgt,
                              const float* __restrict__ bias,
                              float* __restrict__ out)
{
    __shared__ float red[256];
    int b = blockIdx.x;
    const float* h = g_h + (size_t)b * V;
    float s = 0.0f;
    for (int k = threadIdx.x; k < V; k += 256) s = fmaf(h[k], wgt[k], s);
    red[threadIdx.x] = s;
    __syncthreads();
    for (int st = 128; st > 0; st >>= 1) {
        if (threadIdx.x < st) red[threadIdx.x] += red[threadIdx.x + st];
        __syncthreads();
    }
    if (threadIdx.x == 0) out[b] = red[0] + bias[0];
}

// =====================================================================
// Decoder pointwise: all TR steps from one h@Whh_dec^T (4 slices).
// =====================================================================
__global__ void dec_point_kernel(const float* __restrict__ bd,
                                 const float* __restrict__ Wid,
                                 const float* __restrict__ xrev)
{
    int idx = blockIdx.x * blockDim.x + threadIdx.x;
    int b = idx / V, j = idx - b * V;
    size_t rp = (size_t)b * G4;
    float bi = bd[j], bf = bd[V + j], bg = bd[2 * V + j], bo = bd[3 * V + j];
#pragma unroll
    for (int s = 0; s < 4; s++) {
        const float* p = g_preK[s] + rp;
        bi += p[j]; bf += p[V + j]; bg += p[2 * V + j]; bo += p[3 * V + j];
    }
    float w0 = Wid[j], w1 = Wid[V + j], w2 = Wid[2 * V + j], w3 = Wid[3 * V + j];
    float ce = g_c[idx];
#pragma unroll
    for (int tr = 0; tr < TR; tr++) {
        float xr = xrev[b * TR + tr];
        float i_ = sigf (bi + xr * w0);
        float f_ = sigf (bf + xr * w1);
        float gg = tanhf(bg + xr * w2);
        float o_ = sigf (bo + xr * w3);
        float cd = f_ * ce + i_ * gg;
        g_hd16[(size_t)(b * TR + tr) * V + j] = __float2half(o_ * tanhf(cd));
    }
}

// =====================================================================
__global__ void dec_out_kernel(const float* __restrict__ fcb,
                               float* __restrict__ out)
{
    int idx = blockIdx.x * blockDim.x + threadIdx.x;   // 64*V exactly
    int m = idx / V, n = idx - m * V;
    float val = g_decK[0][idx] + g_decK[1][idx] + g_decK[2][idx]
              + g_decK[3][idx] + fcb[n];
    int b = m >> 2, tr = m & 3;
    size_t base = 16 + (size_t)(b * 12 + tr * 3) * V + n;
    out[base]         = val;
    out[base + V]     = val;
    out[base + 2 * V] = val;
}

// =====================================================================
extern "C" void kernel_launch(void* const* d_in, const int* in_sizes, int n_in,
                              void* d_out, int out_size)
{
    (void)in_sizes; (void)n_in; (void)out_size;
    const float* x        = (const float*)d_in[0];
    const float* x_rev    = (const float*)d_in[1];
    const float* W_ih_enc = (const float*)d_in[2];
    const float* W_hh_enc = (const float*)d_in[3];
    const float* b_enc    = (const float*)d_in[4];
    const float* fc_enc_w = (const float*)d_in[5];
    const float* fc_enc_b = (const float*)d_in[6];
    const float* W_ih_dec = (const float*)d_in[7];
    const float* W_hh_dec = (const float*)d_in[8];
    const float* b_dec    = (const float*)d_in[9];
    const float* fc_dec_w = (const float*)d_in[10];
    const float* fc_dec_b = (const float*)d_in[11];
    float* out = (float*)d_out;

    __half *whh16_p, *x16_p, *h16_p, *hd16_p;
    float  *xgK_p, *preK_p, *decK_p;
    cudaGetSymbolAddress((void**)&whh16_p, g_whh16);
    cudaGetSymbolAddress((void**)&x16_p,   g_x16);
    cudaGetSymbolAddress((void**)&h16_p,   g_h16);
    cudaGetSymbolAddress((void**)&hd16_p,  g_hd16);
    cudaGetSymbolAddress((void**)&xgK_p,   g_xgK);
    cudaGetSymbolAddress((void**)&preK_p,  g_preK);
    cudaGetSymbolAddress((void**)&decK_p,  g_decK);

    // 0) x -> fp16 (small stream)
    conv16_kernel<<<(128 * V / 8 + 255) / 256, 256>>>(x, x16_p, 128 * V / 8);

    // 1) xg = x @ W_ih_enc^T (fp32 W converted in-register), K-split 2
    gemm16<128, 32, false, false><<<dim3(G4 / BN, 2), 256>>>(
        x16_p, W_ih_enc, xgK_p, G4, V / 2, nullptr);

    // 2) encoder step 0
    step0_kernel<<<BSZ * V / 256, 256>>>(b_enc);

    // 3) step 1: GEMM reads fp32 W_hh_enc, converts + writes fp16 copy
    gemm16<16, 64, false, true><<<dim3(G4 / BN, 4), 256>>>(
        h16_p, W_hh_enc, preK_p, G4, V / 4, whh16_p);
    rec_point_kernel<<<BSZ * V / 256, 256>>>(1, b_enc, 4);

    // 4) steps 2..7: cp.async-pipelined fp16 GEMM, K-split 8
    for (int t = 2; t < TT; t++) {
        gemm16_ca<32, 4><<<dim3(G4 / BN, 8), 256>>>(h16_p, whh16_p, preK_p, G4, V / 8);
        rec_point_kernel<<<BSZ * V / 256, 256>>>(t, b_enc, 8);
    }

    // 5) enc_out -> d_out[0..15]
    fc_enc_kernel<<<BSZ, 256>>>(fc_enc_w, fc_enc_b, out);

    // 6) decoder pre = h_enc @ W_hh_dec^T (fp32 W, single use), then gates
    gemm16<16, 64, false, false><<<dim3(G4 / BN, 4), 256>>>(
        h16_p, W_hh_dec, preK_p, G4, V / 4, nullptr);
    dec_point_kernel<<<BSZ * V / 256, 256>>>(b_dec, W_ih_dec, x_rev);

    // 7) dec = h_d @ fc_dec_w^T (fp32 W), then bias + repeat(3) scatter
    gemm16<64, 32, false, false><<<dim3(V / BN, 4), 256>>>(
        hd16_p, fc_dec_w, decK_p, V, V / 4, nullptr);
    dec_out_kernel<<<BSZ * TR * V / 256, 256>>>(fc_dec_b, out);
}